// round 10
// baseline (speedup 1.0000x reference)
#include <cuda_runtime.h>
#include <cuda_fp16.h>
#include <cstdint>
#include <math.h>

#define BB   16
#define CC   256
#define HWN  4096
#define KK   4
#define HIDN 512
#define EPS_W 1e-8f
#define LN_EPS 1e-5f
#define SCALE 0.0625f   // C^-0.5 = 1/16
#define NBLK 512

// ---------------- scratch (static device globals; no allocation) ----------------
static __device__ __align__(16) __half g_xnl [BB*HWN*CC];  // LN'd input (b,n,c) fp16
static __device__ __align__(16) float g_slots[BB*KK*CC];
static __device__ __align__(16) float g_qt  [BB*KK*CC];
static __device__            float g_qb  [BB*KK];
static __device__ __align__(16) float g_A   [BB*KK*CC];
static __device__            float g_S   [BB*KK];
static __device__ __align__(16) float g_spre[BB*KK*CC];
static __device__ __align__(16) float g_h   [BB*KK*HIDN];
static __device__ __align__(16) float g_Wvu [CC*CC];   // (Wu2@Wv)[d][c]
static __device__            float g_bvu [CC];
static __device__ __align__(16) float g_Wqk [CC*CC];   // scale*(Wk^T Wq)[c_out][e]
static __device__            float g_qtb [CC];
static __device__ __align__(16) float g_wqbk[CC];
static __device__            float g_bqbk;

// grid barrier state
static __device__ unsigned int g_bar_count = 0;
static __device__ volatile unsigned int g_bar_gen = 0;

// attn tile = 64 tokens, x stride 129 words (129 mod 32 = 1: conflict-free)
#define TOK 64
#define XSTR 129
#define OFF_SX     0                              // 64*129*4 = 33024
#define OFF_QT     33024                          // 1024 floats = 4096
#define OFF_PART   37120                          // 256*4 floats = 4096
#define OFF_SA     41216                          // 64*4 floats = 1024
#define OFF_QB     42240                          // 16
#define OFF_SRED   42256                          // 64
#define SMEM_DYN   44032

// update-phase view
#define U_OFF_IN    0            // up to 4*512 floats = 8192
#define U_OFF_IN2   8192         // 4*256 floats = 4096
#define U_OFF_SLAB  12288        // slabs <= 16896
#define U_OFF_RED   29440        // 256 floats

__device__ __forceinline__ float gelu_f(float x) {
    return 0.5f * x * (1.0f + erff(x * 0.70710678118654752f));
}

__device__ __forceinline__ void grid_bar() {
    __syncthreads();
    if (threadIdx.x == 0) {
        __threadfence();
        unsigned int gen = g_bar_gen;
        if (atomicAdd(&g_bar_count, 1u) == NBLK - 1) {
            atomicExch(&g_bar_count, 0u);
            __threadfence();
            g_bar_gen = gen + 1;
        } else {
            while (g_bar_gen == gen) { __nanosleep(64); }
        }
        __threadfence();
    }
    __syncthreads();
}

// LN of 4 rows (stride 256) in smem `sin`, in place; red = 256-float scratch.
__device__ __forceinline__ void ln_apply4(float* sin, float* red,
                                          const float* __restrict__ gg,
                                          const float* __restrict__ bb, int tid) {
    int r = tid >> 6, t = tid & 63;
    float4 v = ((const float4*)(sin + r * 256))[t];
    float s = v.x + v.y + v.z + v.w;
    float q = v.x * v.x + v.y * v.y + v.z * v.z + v.w * v.w;
    #pragma unroll
    for (int off = 16; off; off >>= 1) {
        s += __shfl_xor_sync(0xffffffffu, s, off);
        q += __shfl_xor_sync(0xffffffffu, q, off);
    }
    int w = tid >> 5;
    if ((tid & 31) == 0) { red[w * 2] = s; red[w * 2 + 1] = q; }
    __syncthreads();
    if (tid < 4) {
        float S = red[tid * 4] + red[tid * 4 + 2];
        float Q = red[tid * 4 + 1] + red[tid * 4 + 3];
        float m = S * (1.0f / 256.0f);
        red[16 + tid * 2] = m;
        red[17 + tid * 2] = rsqrtf(Q * (1.0f / 256.0f) - m * m + LN_EPS);
    }
    __syncthreads();
    #pragma unroll
    for (int i = 0; i < 4; i++) {
        int idx = i * 256 + tid; int rr = idx >> 8, c = idx & 255;
        float m = red[16 + rr * 2], rstd = red[17 + rr * 2];
        sin[rr * 256 + c] = (sin[rr * 256 + c] - m) * rstd * gg[c] + bb[c];
    }
    __syncthreads();
}

// ---------------- phase-0 device fns ----------------
__device__ void prep_unit(int bid, char* smraw, int tid,
                          const float* __restrict__ Wq, const float* __restrict__ Wk,
                          const float* __restrict__ bq, const float* __restrict__ Wv,
                          const float* __restrict__ bv, const float* __restrict__ Wu) {
    float* sbuf = (float*)smraw;               // 32*260 floats
    float* wcs  = sbuf + 32 * 260;             // 1024 floats
    if (bid < 64) {
        int d0 = bid * 4;
        for (int idx = tid; idx < CC * 4; idx += 256) {
            int dl = idx & 3, e = idx >> 2;
            wcs[e * 4 + dl] = Wu[(size_t)(d0 + dl) * 512 + 256 + e];
        }
        __syncthreads();
        float a0 = 0.f, a1 = 0.f, a2 = 0.f, a3 = 0.f;
        for (int ch = 0; ch < 8; ch++) {
            #pragma unroll 8
            for (int it = 0; it < 32; it++)
                sbuf[it * 260 + tid] = Wv[(size_t)(ch * 32 + it) * CC + tid];
            __syncthreads();
            #pragma unroll 8
            for (int el = 0; el < 32; el++) {
                float x = sbuf[el * 260 + tid];
                float4 w = *(const float4*)&wcs[(ch * 32 + el) * 4];
                a0 += w.x * x; a1 += w.y * x; a2 += w.z * x; a3 += w.w * x;
            }
            __syncthreads();
        }
        g_Wvu[(size_t)(d0 + 0) * CC + tid] = a0;
        g_Wvu[(size_t)(d0 + 1) * CC + tid] = a1;
        g_Wvu[(size_t)(d0 + 2) * CC + tid] = a2;
        g_Wvu[(size_t)(d0 + 3) * CC + tid] = a3;
        if (tid < 4) {
            float s = 0.f;
            for (int e = 0; e < CC; e++)
                s += Wu[(size_t)(d0 + tid) * 512 + 256 + e] * bv[e];
            g_bvu[d0 + tid] = s;
        }
    } else {
        int c0 = (bid - 64) * 4;
        float a0 = 0.f, a1 = 0.f, a2 = 0.f, a3 = 0.f;
        for (int ch = 0; ch < 8; ch++) {
            #pragma unroll 8
            for (int it = 0; it < 32; it++)
                sbuf[it * 260 + tid] = Wq[(size_t)(ch * 32 + it) * CC + tid];
            if (tid < 128) {
                int dl = tid >> 2, cl = tid & 3;
                wcs[dl * 4 + cl] = Wk[(size_t)(ch * 32 + dl) * CC + c0 + cl];
            }
            __syncthreads();
            #pragma unroll 8
            for (int dl = 0; dl < 32; dl++) {
                float x = sbuf[dl * 260 + tid];
                a0 += wcs[dl * 4 + 0] * x; a1 += wcs[dl * 4 + 1] * x;
                a2 += wcs[dl * 4 + 2] * x; a3 += wcs[dl * 4 + 3] * x;
            }
            __syncthreads();
        }
        g_Wqk[(size_t)(c0 + 0) * CC + tid] = SCALE * a0;
        g_Wqk[(size_t)(c0 + 1) * CC + tid] = SCALE * a1;
        g_Wqk[(size_t)(c0 + 2) * CC + tid] = SCALE * a2;
        g_Wqk[(size_t)(c0 + 3) * CC + tid] = SCALE * a3;
        if (tid < 4) {
            float s = 0.f;
            for (int d = 0; d < CC; d++) s += Wk[(size_t)d * CC + c0 + tid] * bq[d];
            g_qtb[c0 + tid] = SCALE * s;
        }
    }
    __syncthreads();
}

__device__ void prep_bias(char* smraw, int tid,
                          const float* __restrict__ Wq, const float* __restrict__ bq,
                          const float* __restrict__ bk) {
    float* sbuf = (float*)smraw;
    float s = 0.f;
    #pragma unroll 8
    for (int d = 0; d < CC; d++) s += Wq[(size_t)d * CC + tid] * bk[d];
    g_wqbk[tid] = SCALE * s;
    sbuf[tid] = bq[tid] * bk[tid];
    __syncthreads();
    #pragma unroll
    for (int st = 128; st > 0; st >>= 1) {
        if (tid < st) sbuf[tid] += sbuf[tid + st];
        __syncthreads();
    }
    if (tid == 0) g_bqbk = SCALE * sbuf[0];
    __syncthreads();
}

// one LN-input tile (32 tokens): t in [0,2048)
__device__ void ln_tile(int t, char* smraw, int tid,
                        const float* __restrict__ x,
                        const float* __restrict__ lg,
                        const float* __restrict__ lb) {
    float* sm = (float*)smraw;        // 256*33
    float* ps = sm + 256 * 33;
    float* pq = ps + 256;
    float* mu = pq + 256;
    float* rs = mu + 32;
    int b = t >> 7;
    int tile = t & 127;
    int n0 = tile * 32;
    __syncthreads();

    const float* xb = x + ((size_t)b * CC) * HWN + n0;
    #pragma unroll 8
    for (int it = 0; it < 32; it++) {
        int idx = it * 256 + tid;
        int n = idx & 31, c = idx >> 5;
        sm[c * 33 + n] = xb[(size_t)c * HWN + n];
    }
    __syncthreads();

    int p = tid >> 5, tn = tid & 31;
    float s = 0.f, sq = 0.f;
    #pragma unroll 8
    for (int cc = 0; cc < 32; cc++) {
        float v = sm[(p * 32 + cc) * 33 + tn];
        s += v; sq += v * v;
    }
    ps[p * 32 + tn] = s; pq[p * 32 + tn] = sq;
    __syncthreads();
    if (tid < 32) {
        float S = 0.f, Q = 0.f;
        #pragma unroll
        for (int i = 0; i < 8; i++) { S += ps[i * 32 + tid]; Q += pq[i * 32 + tid]; }
        float m = S * (1.0f / 256.0f);
        float var = Q * (1.0f / 256.0f) - m * m;
        mu[tid] = m;
        rs[tid] = rsqrtf(var + LN_EPS);
    }
    __syncthreads();

    float gc = lg[tid], bc = lb[tid];
    __half* out = g_xnl + ((size_t)(b * HWN + n0)) * CC;
    #pragma unroll 8
    for (int it = 0; it < 32; it++) {
        float v = sm[tid * 33 + it];
        out[(size_t)it * CC + tid] = __float2half_rn((v - mu[it]) * rs[it] * gc + bc);
    }
}

// ---------------- attn tile: 64 tokens ----------------
__device__ __forceinline__ void attn_tile(int t, char* smraw, int tid) {
    unsigned int* sx = (unsigned int*)(smraw + OFF_SX);  // [64][129]
    float*  sqtf  = (float*) (smraw + OFF_QT);           // packed [c2][sub][k]
    float*  spart = (float*) (smraw + OFF_PART);         // [256] float4
    float*  sa    = (float*) (smraw + OFF_SA);           // [64] float4
    float*  sqb   = (float*) (smraw + OFF_QB);
    float*  sred  = (float*) (smraw + OFF_SRED);

    int b = t >> 6;
    int tile = t & 63;
    int n0 = tile * TOK;

    const uint4* gx = (const uint4*)(g_xnl + ((size_t)(b * HWN + n0)) * CC);
    #pragma unroll
    for (int it = 0; it < 8; it++) {
        int idx = it * 256 + tid;          // 0..2047
        int n = idx >> 5, c8 = idx & 31;
        uint4 u = gx[idx];
        unsigned int* dst = sx + n * XSTR + c8 * 4;
        dst[0] = u.x; dst[1] = u.y; dst[2] = u.z; dst[3] = u.w;
    }
    #pragma unroll
    for (int it = 0; it < 4; it++) {
        int idx = it * 256 + tid;          // 0..1023
        int k = idx & 3, sub = (idx >> 2) & 1, c2 = idx >> 3;
        sqtf[c2 * 8 + sub * 4 + k] = g_qt[(b * KK + k) * CC + c2 * 2 + sub];
    }
    if (tid < 4) sqb[tid] = g_qb[b * KK + tid];
    __syncthreads();

    // phase 1: thread = (token n, quarter qd); 32 words each
    {
        int n = tid & 63, qd = tid >> 6;
        const unsigned int* xrow = sx + n * XSTR + qd * 32;
        const float4* q4 = (const float4*)sqtf + qd * 64;
        float p0 = 0.f, p1 = 0.f, p2 = 0.f, p3 = 0.f;
        #pragma unroll 8
        for (int i = 0; i < 32; i++) {
            __half2 hx = *(const __half2*)&xrow[i];
            float2 xf = __half22float2(hx);
            float4 qa = q4[2 * i];
            float4 qb = q4[2 * i + 1];
            p0 += xf.x * qa.x + xf.y * qb.x;
            p1 += xf.x * qa.y + xf.y * qb.y;
            p2 += xf.x * qa.z + xf.y * qb.z;
            p3 += xf.x * qa.w + xf.y * qb.w;
        }
        ((float4*)spart)[tid] = make_float4(p0, p1, p2, p3);
    }
    __syncthreads();

    // softmax: threads 0..63
    if (tid < 64) {
        float4 pa = ((const float4*)spart)[tid];
        float4 pb = ((const float4*)spart)[tid + 64];
        float4 pc = ((const float4*)spart)[tid + 128];
        float4 pd = ((const float4*)spart)[tid + 192];
        float l0 = pa.x + pb.x + pc.x + pd.x + sqb[0];
        float l1 = pa.y + pb.y + pc.y + pd.y + sqb[1];
        float l2 = pa.z + pb.z + pc.z + pd.z + sqb[2];
        float l3 = pa.w + pb.w + pc.w + pd.w + sqb[3];
        float mx = fmaxf(fmaxf(l0, l1), fmaxf(l2, l3));
        float e0 = __expf(l0 - mx), e1 = __expf(l1 - mx);
        float e2 = __expf(l2 - mx), e3 = __expf(l3 - mx);
        float inv = __fdividef(1.0f, e0 + e1 + e2 + e3);
        float a0 = e0 * inv, a1 = e1 * inv, a2 = e2 * inv, a3 = e3 * inv;
        ((float4*)sa)[tid] = make_float4(a0, a1, a2, a3);
        float s0 = a0, s1 = a1, s2 = a2, s3 = a3;
        #pragma unroll
        for (int off = 16; off; off >>= 1) {
            s0 += __shfl_xor_sync(0xffffffffu, s0, off);
            s1 += __shfl_xor_sync(0xffffffffu, s1, off);
            s2 += __shfl_xor_sync(0xffffffffu, s2, off);
            s3 += __shfl_xor_sync(0xffffffffu, s3, off);
        }
        if ((tid & 31) == 0) {
            int w = tid >> 5;
            sred[w * 4 + 0] = s0; sred[w * 4 + 1] = s1;
            sred[w * 4 + 2] = s2; sred[w * 4 + 3] = s3;
        }
    }
    __syncthreads();
    if (tid < 4) atomicAdd(&g_S[b * KK + tid], sred[tid] + sred[4 + tid]);

    // phase 2: warp = 32-channel slice (16 words), lane halves split 64 tokens
    {
        int w = tid >> 5, L = tid & 31;
        int word = w * 16 + (L & 15);
        bool hi = (L >= 16);
        float2 a0 = {0.f, 0.f}, a1 = {0.f, 0.f}, a2 = {0.f, 0.f}, a3 = {0.f, 0.f};
        #pragma unroll 8
        for (int t2 = 0; t2 < 32; t2++) {
            int nn = hi ? (32 + ((t2 + 16) & 31)) : t2;
            __half2 hx = *(const __half2*)&sx[nn * XSTR + word];
            float2 xf = __half22float2(hx);
            float4 av = ((const float4*)sa)[nn];
            a0.x += av.x * xf.x; a0.y += av.x * xf.y;
            a1.x += av.y * xf.x; a1.y += av.y * xf.y;
            a2.x += av.z * xf.x; a2.y += av.z * xf.y;
            a3.x += av.w * xf.x; a3.y += av.w * xf.y;
        }
        a0.x += __shfl_down_sync(0xffffffffu, a0.x, 16);
        a0.y += __shfl_down_sync(0xffffffffu, a0.y, 16);
        a1.x += __shfl_down_sync(0xffffffffu, a1.x, 16);
        a1.y += __shfl_down_sync(0xffffffffu, a1.y, 16);
        a2.x += __shfl_down_sync(0xffffffffu, a2.x, 16);
        a2.y += __shfl_down_sync(0xffffffffu, a2.y, 16);
        a3.x += __shfl_down_sync(0xffffffffu, a3.x, 16);
        a3.y += __shfl_down_sync(0xffffffffu, a3.y, 16);
        if (!hi) {
            int c = 2 * word;
            float* A0 = g_A + (b * KK + 0) * CC + c;
            float* A1 = g_A + (b * KK + 1) * CC + c;
            float* A2 = g_A + (b * KK + 2) * CC + c;
            float* A3 = g_A + (b * KK + 3) * CC + c;
            atomicAdd(A0, a0.x); atomicAdd(A0 + 1, a0.y);
            atomicAdd(A1, a1.x); atomicAdd(A1 + 1, a1.y);
            atomicAdd(A2, a2.x); atomicAdd(A2 + 1, a2.y);
            atomicAdd(A3, a3.x); atomicAdd(A3 + 1, a3.y);
        }
    }
    __syncthreads();
}

// ---------------- qt stage: 512 blocks = 16 rg x 32 os (8 outputs each) ---------
__device__ __forceinline__ void qt_stage(char* smraw, int bid, int tid,
                                         const float* lsg, const float* lsb,
                                         int zeroAS) {
    float* uin  = (float*)(smraw + U_OFF_IN);
    float* slab = (float*)(smraw + U_OFF_SLAB);   // 8 x 264
    float* red  = (float*)(smraw + U_OFF_RED);
    int rg = bid >> 5, os = bid & 31;

    #pragma unroll
    for (int i = 0; i < 4; i++) {
        int idx = i * 256 + tid; int r = idx >> 8, c = idx & 255;
        uin[r * 256 + c] = g_slots[(rg * 4 + r) * 256 + c];
    }
    #pragma unroll
    for (int i = 0; i < 8; i++) {
        int idx = i * 256 + tid; int j = idx >> 8, c = idx & 255;
        slab[j * 264 + c] = g_Wqk[(size_t)(os * 8 + j) * 256 + c];
    }
    __syncthreads();
    ln_apply4(uin, red, lsg, lsb, tid);

    if (os == 0) {
        int r = tid >> 6, t = tid & 63;
        float4 v = ((const float4*)(uin + r * 256))[t];
        float4 w = ((const float4*)g_wqbk)[t];
        float s = v.x * w.x + v.y * w.y + v.z * w.z + v.w * w.w;
        #pragma unroll
        for (int off = 16; off; off >>= 1) s += __shfl_xor_sync(0xffffffffu, s, off);
        if ((tid & 31) == 0) red[(tid >> 5) * 2] = s;
        __syncthreads();
        if (tid < 4) g_qb[rg * 4 + tid] = red[tid * 4] + red[tid * 4 + 2] + g_bqbk;
    }

    int r = tid >> 6, j = (tid >> 3) & 7, cq = tid & 7;
    float acc = 0.f;
    #pragma unroll 8
    for (int ci = 0; ci < 32; ci++) {
        int c = cq + ci * 8;
        acc += uin[r * 256 + c] * slab[j * 264 + c];
    }
    acc += __shfl_xor_sync(0xffffffffu, acc, 1);
    acc += __shfl_xor_sync(0xffffffffu, acc, 2);
    acc += __shfl_xor_sync(0xffffffffu, acc, 4);
    if (cq == 0) {
        int cc = os * 8 + j, row = rg * 4 + r;
        g_qt[row * 256 + cc] = acc + g_qtb[cc];
    }
    if (zeroAS) {
        if (tid < 32) {
            int r2 = tid >> 3, j2 = tid & 7;
            g_A[(rg * 4 + r2) * 256 + os * 8 + j2] = 0.f;
        }
        if (os == 0 && tid < 4) g_S[rg * 4 + tid] = 0.f;
    }
}

// ---------------- THE kernel ----------------
__global__ void __launch_bounds__(256, 4) k_mega(
    const float* __restrict__ x,
    const float* __restrict__ lig,  const float* __restrict__ lib,
    const float* __restrict__ smu,  const float* __restrict__ sls,
    const float* __restrict__ noise,
    const float* __restrict__ lsg,  const float* __restrict__ lsb,
    const float* __restrict__ lmg,  const float* __restrict__ lmb,
    const float* __restrict__ Wq,   const float* __restrict__ bq,
    const float* __restrict__ Wk,   const float* __restrict__ bk,
    const float* __restrict__ Wv,   const float* __restrict__ bv,
    const float* __restrict__ Wu,   const float* __restrict__ bu,
    const float* __restrict__ W1,   const float* __restrict__ b1,
    const float* __restrict__ W2,   const float* __restrict__ b2,
    const float* __restrict__ We1,  const float* __restrict__ be1,
    const float* __restrict__ We2,  const float* __restrict__ be2,
    float* __restrict__ out) {
    extern __shared__ __align__(16) char smraw[];
    float* uin  = (float*)(smraw + U_OFF_IN);
    float* uin2 = (float*)(smraw + U_OFF_IN2);
    float* slab = (float*)(smraw + U_OFF_SLAB);
    float* slab2 = slab + 8 * 264;
    float* red  = (float*)(smraw + U_OFF_RED);
    int bid = blockIdx.x;
    int tid = threadIdx.x;
    int rg = bid >> 5, os = bid & 31;

    // ================= phase 0 =================
    if (bid < 128) {
        prep_unit(bid, smraw, tid, Wq, Wk, bq, Wv, bv, Wu);
    } else if (bid == 128) {
        prep_bias(smraw, tid, Wq, bq, bk);
    } else if (bid < 193) {
        int row = bid - 129;
        float ns = smu[tid] + expf(sls[tid]) * noise[row * 256 + tid];
        g_slots[row * 256 + tid] = ns;
        g_A[row * 256 + tid] = 0.f;
        if (tid == 0) g_S[row] = 0.f;
    }
    if (bid <= 128) {
        ln_tile(bid, smraw, tid, x, lig, lib);     // tiles 0..128
    } else {
        for (int t = 129 + (bid - 129); t < 2048; t += 383)
            ln_tile(t, smraw, tid, x, lig, lib);
    }
    grid_bar();
    qt_stage(smraw, bid, tid, lsg, lsb, 0);
    grid_bar();

    // ================= 3 iterations =================
    for (int it = 0; it < 3; it++) {
        int last = (it == 2);
        attn_tile(bid, smraw, tid);
        attn_tile(bid + 512, smraw, tid);
        grid_bar();

        // ---- S1: spre (8 outputs per block) ----
        {
            #pragma unroll
            for (int i = 0; i < 4; i++) {
                int idx = i * 256 + tid; int r = idx >> 8, c = idx & 255;
                int row = rg * 4 + r;
                uin[r * 256 + c] = g_slots[row * 256 + c];
                float Sv = g_S[row];
                uin2[r * 256 + c] = g_A[row * 256 + c] * (1.0f / (Sv + EPS_W));
            }
            #pragma unroll
            for (int i = 0; i < 8; i++) {
                int idx = i * 256 + tid; int j = idx >> 8, c = idx & 255;
                slab [j * 264 + c] = Wu[(size_t)(os * 8 + j) * 512 + c];
                slab2[j * 264 + c] = g_Wvu[(size_t)(os * 8 + j) * 256 + c];
            }
            __syncthreads();
            int r = tid >> 6, j = (tid >> 3) & 7, cq = tid & 7;
            float acc = 0.f;
            #pragma unroll 8
            for (int ci = 0; ci < 32; ci++) {
                int c = cq + ci * 8;
                acc += uin[r * 256 + c] * slab[j * 264 + c]
                     + uin2[r * 256 + c] * slab2[j * 264 + c];
            }
            acc += __shfl_xor_sync(0xffffffffu, acc, 1);
            acc += __shfl_xor_sync(0xffffffffu, acc, 2);
            acc += __shfl_xor_sync(0xffffffffu, acc, 4);
            if (cq == 0) {
                int d = os * 8 + j, row = rg * 4 + r;
                float Sv = g_S[row];
                float beta = Sv / (Sv + EPS_W);
                g_spre[row * 256 + d] = acc + bu[d] + uin[r * 256 + d]
                                      + beta * g_bvu[d];
            }
        }
        grid_bar();

        // ---- S2: h = gelu(LN_mlp(spre) @ W1^T + b1), 16 outputs/block ----
        {
            #pragma unroll
            for (int i = 0; i < 4; i++) {
                int idx = i * 256 + tid; int r = idx >> 8, c = idx & 255;
                uin[r * 256 + c] = g_spre[(rg * 4 + r) * 256 + c];
            }
            #pragma unroll
            for (int i = 0; i < 16; i++) {
                int idx = i * 256 + tid; int j = idx >> 8, c = idx & 255;
                slab[j * 260 + c] = W1[(size_t)(os * 16 + j) * 256 + c];
            }
            __syncthreads();
            ln_apply4(uin, red, lmg, lmb, tid);
            int r = tid >> 6, j = (tid >> 2) & 15, cq = tid & 3;
            float acc = 0.f;
            #pragma unroll 8
            for (int ci = 0; ci < 64; ci++) {
                int c = cq + ci * 4;
                acc += uin[r * 256 + c] * slab[j * 260 + c];
            }
            acc += __shfl_xor_sync(0xffffffffu, acc, 1);
            acc += __shfl_xor_sync(0xffffffffu, acc, 2);
            if (cq == 0) {
                int jj = os * 16 + j, row = rg * 4 + r;
                g_h[row * 512 + jj] = gelu_f(acc + b1[jj]);
            }
        }
        grid_bar();

        // ---- S3: slots = spre + h @ W2^T + b2, 8 outputs/block ----
        {
            #pragma unroll
            for (int i = 0; i < 8; i++) {
                int idx = i * 256 + tid; int r = idx >> 9, c = idx & 511;
                uin[r * 512 + c] = g_h[(rg * 4 + r) * 512 + c];
            }
            #pragma unroll
            for (int i = 0; i < 16; i++) {
                int idx = i * 256 + tid; int j = idx >> 9, c = idx & 511;
                slab[j * 520 + c] = W2[(size_t)(os * 8 + j) * 512 + c];
            }
            __syncthreads();
            int r = tid >> 6, j = (tid >> 3) & 7, cq = tid & 7;
            float acc = 0.f;
            #pragma unroll 8
            for (int ci = 0; ci < 64; ci++) {
                int c = cq + ci * 8;
                acc += uin[r * 512 + c] * slab[j * 520 + c];
            }
            acc += __shfl_xor_sync(0xffffffffu, acc, 1);
            acc += __shfl_xor_sync(0xffffffffu, acc, 2);
            acc += __shfl_xor_sync(0xffffffffu, acc, 4);
            if (cq == 0) {
                int d = os * 8 + j, row = rg * 4 + r;
                float val = acc + b2[d] + g_spre[row * 256 + d];
                g_slots[row * 256 + d] = val;
                if (last) out[row * 256 + d] = val;
            }
        }
        grid_bar();

        if (!last) {
            qt_stage(smraw, bid, tid, lsg, lsb, 1);
            grid_bar();
        } else {
            // ---- head: e = gelu(We1 @ slots + be1), 4 outputs/block ----
            #pragma unroll
            for (int i = 0; i < 4; i++) {
                int idx = i * 256 + tid; int r = idx >> 8, c = idx & 255;
                uin[r * 256 + c] = g_slots[(rg * 4 + r) * 256 + c];
            }
            #pragma unroll
            for (int i = 0; i < 4; i++) {
                int idx = i * 256 + tid; int j = idx >> 8, c = idx & 255;
                slab[j * 272 + c] = We1[(size_t)(os * 4 + j) * 256 + c];
            }
            __syncthreads();
            int r = tid >> 6, j = (tid >> 4) & 3, c16 = tid & 15;
            float acc = 0.f;
            #pragma unroll 8
            for (int ci = 0; ci < 16; ci++) {
                int c = c16 + ci * 16;
                acc += uin[r * 256 + c] * slab[j * 272 + c];
            }
            acc += __shfl_xor_sync(0xffffffffu, acc, 1);
            acc += __shfl_xor_sync(0xffffffffu, acc, 2);
            acc += __shfl_xor_sync(0xffffffffu, acc, 4);
            acc += __shfl_xor_sync(0xffffffffu, acc, 8);
            if (c16 == 0) {
                int jj = os * 4 + j, row = rg * 4 + r;
                g_qt[row * 256 + jj] = gelu_f(acc + be1[jj]);
            }
            grid_bar();
            if (bid == 0) {
                int row = tid >> 2, p = tid & 3;
                float a2 = 0.f;
                #pragma unroll 8
                for (int k2 = 0; k2 < 32; k2++) {
                    int j2 = p + k2 * 4;
                    a2 += g_qt[row * 256 + j2] * We2[j2];
                }
                a2 += __shfl_xor_sync(0xffffffffu, a2, 1);
                a2 += __shfl_xor_sync(0xffffffffu, a2, 2);
                if (p == 0)
                    out[BB * KK * CC + row] = 1.0f / (1.0f + expf(-(a2 + be2[0])));
            }
        }
    }
}

// ---------------- host ----------------
extern "C" void kernel_launch(void* const* d_in, const int* in_sizes, int n_in,
                              void* d_out, int out_size) {
    const float* x        = (const float*)d_in[0];
    const float* noise    = (const float*)d_in[1];
    const float* slot_mu  = (const float*)d_in[2];
    const float* slot_ls  = (const float*)d_in[3];
    const float* ln_in_g  = (const float*)d_in[4];
    const float* ln_in_b  = (const float*)d_in[5];
    const float* ln_sl_g  = (const float*)d_in[6];
    const float* ln_sl_b  = (const float*)d_in[7];
    const float* ln_mlp_g = (const float*)d_in[8];
    const float* ln_mlp_b = (const float*)d_in[9];
    const float* Wq = (const float*)d_in[10];
    const float* bq = (const float*)d_in[11];
    const float* Wk = (const float*)d_in[12];
    const float* bk = (const float*)d_in[13];
    const float* Wv = (const float*)d_in[14];
    const float* bv = (const float*)d_in[15];
    const float* Wu = (const float*)d_in[16];
    const float* bu = (const float*)d_in[17];
    const float* W1 = (const float*)d_in[18];
    const float* b1 = (const float*)d_in[19];
    const float* W2 = (const float*)d_in[20];
    const float* b2 = (const float*)d_in[21];
    const float* We1 = (const float*)d_in[22];
    const float* be1 = (const float*)d_in[23];
    const float* We2 = (const float*)d_in[24];
    const float* be2 = (const float*)d_in[25];
    float* out = (float*)d_out;

    static int attr_set = 0;
    if (!attr_set) {
        cudaFuncSetAttribute(k_mega, cudaFuncAttributeMaxDynamicSharedMemorySize,
                             SMEM_DYN);
        attr_set = 1;
    }

    k_mega<<<NBLK, 256, SMEM_DYN>>>(x, ln_in_g, ln_in_b,
                                    slot_mu, slot_ls, noise,
                                    ln_sl_g, ln_sl_b, ln_mlp_g, ln_mlp_b,
                                    Wq, bq, Wk, bk, Wv, bv, Wu, bu,
                                    W1, b1, W2, b2,
                                    We1, be1, We2, be2, out);
}